// round 5
// baseline (speedup 1.0000x reference)
#include <cuda_runtime.h>
#include <cuda_bf16.h>

// Problem constants (fixed by the reference setup_inputs)
#define BB 2
#define NN 8192
#define MM 32768
#define SS 4096
#define NQ (BB * SS)          // 8192 queries
#define NT (BB * MM)          // 65536 targets

// Grid for spatial hashing: 32^3 cells per batch over [-6.4, 6.4], h = 0.4
#define G 32
#define GLO (-6.4f)
#define GH 0.4f
#define GINVH 2.5f
#define CELLS_PER_B (G * G * G)       // 32768
#define NC (BB * CELLS_PER_B)         // 65536

#define RBLOCKS 64

// Device scratch (no allocations allowed)
__device__ float4 g_target4[NT];     // (x, y, z, cell-id-as-int-bits)
__device__ float4 g_tsorted[NT];     // cell-sorted targets (x, y, z, unused)
__device__ float4 g_pred4[NQ];       // gathered query points (x, y, z, 0)
__device__ int    g_count[NC];       // per-cell counts
__device__ int    g_fill[NC];        // scatter cursors
__device__ int    g_cellstart[NC + 1];
__device__ int    g_minbuf[NQ];      // min d^2 bits per query
__device__ float  g_partial[RBLOCKS];

__global__ void zero_kernel() {
    int i = blockIdx.x * blockDim.x + threadIdx.x;
    if (i < NC) { g_count[i] = 0; g_fill[i] = 0; }
}

__device__ __forceinline__ int cell_coord(float v) {
    int c = (int)((v - GLO) * GINVH);
    return min(max(c, 0), G - 1);
}

// Compute target point records + per-cell histogram
__global__ void count_kernel(const float* __restrict__ target) {
    int i = blockIdx.x * blockDim.x + threadIdx.x;
    if (i < NT) {
        float x = target[3 * i + 0];
        float y = target[3 * i + 1];
        float z = target[3 * i + 2];
        int b = i / MM;
        int cell = b * CELLS_PER_B +
                   ((cell_coord(z) * G + cell_coord(y)) * G + cell_coord(x));
        g_target4[i] = make_float4(x, y, z, __int_as_float(cell));
        atomicAdd(&g_count[cell], 1);
    }
}

// Exclusive prefix scan over NC=65536 counts; single block of 1024 threads.
__global__ void __launch_bounds__(1024) scan_kernel() {
    __shared__ int wsum[32];
    const int tid = threadIdx.x;
    const int base = tid * (NC / 1024);   // 64 per thread
    int s = 0;
    for (int k = 0; k < NC / 1024; k++) s += g_count[base + k];

    int lane = tid & 31, wid = tid >> 5;
    int v = s;
#pragma unroll
    for (int o = 1; o < 32; o <<= 1) {
        int t = __shfl_up_sync(0xFFFFFFFFu, v, o);
        if (lane >= o) v += t;
    }
    if (lane == 31) wsum[wid] = v;
    __syncthreads();
    if (wid == 0) {
        int w = wsum[lane];
#pragma unroll
        for (int o = 1; o < 32; o <<= 1) {
            int t = __shfl_up_sync(0xFFFFFFFFu, w, o);
            if (lane >= o) w += t;
        }
        wsum[lane] = w;
    }
    __syncthreads();
    int excl = v - s + (wid > 0 ? wsum[wid - 1] : 0);
    int run = excl;
    for (int k = 0; k < NC / 1024; k++) {
        int c = g_count[base + k];
        g_cellstart[base + k] = run;
        run += c;
    }
    if (tid == 1023) g_cellstart[NC] = run;
}

__global__ void scatter_kernel() {
    int i = blockIdx.x * blockDim.x + threadIdx.x;
    if (i < NT) {
        float4 t = g_target4[i];
        int cell = __float_as_int(t.w);
        int pos = g_cellstart[cell] + atomicAdd(&g_fill[cell], 1);
        g_tsorted[pos] = t;
    }
}

// Gather query points. idx is int32 on device (JAX x64-disabled coerces int64).
__global__ void prep_pred_kernel(const float* __restrict__ pred,
                                 const int* __restrict__ idx) {
    int i = blockIdx.x * blockDim.x + threadIdx.x;
    if (i < NQ) {
        int b = i / SS;
        int s = i % SS;
        int j = min(max(idx[s], 0), NN - 1);
        const float* p = pred + ((long long)b * NN + j) * 3;
        g_pred4[i] = make_float4(p[0], p[1], p[2], 0.0f);
    }
}

// Warp-per-query expanding-shell exact nearest neighbor.
#define QTPB 256
__global__ void __launch_bounds__(QTPB) query_kernel() {
    const int warp = blockIdx.x * (QTPB / 32) + (threadIdx.x >> 5);  // query id
    const int lane = threadIdx.x & 31;
    if (warp >= NQ) return;

    float4 q = g_pred4[warp];
    const float qx = q.x, qy = q.y, qz = q.z;
    const int hx = cell_coord(qx);
    const int hy = cell_coord(qy);
    const int hz = cell_coord(qz);
    const int cbase = (warp / SS) * CELLS_PER_B;

    float lbest = __int_as_float(0x7F800000);
    float wbest = lbest;

    for (int r = 0; r < G; r++) {
        // Visit all cells at Chebyshev ring exactly r
        for (int dz = -r; dz <= r; dz++) {
            int cz = hz + dz;
            if ((unsigned)cz >= G) continue;
            int az = abs(dz);
            for (int dy = -r; dy <= r; dy++) {
                int cy = hy + dy;
                if ((unsigned)cy >= G) continue;
                int ayz = max(az, abs(dy));
                for (int dx = -r; dx <= r; dx++) {
                    if (max(ayz, abs(dx)) != r) continue;
                    int cx = hx + dx;
                    if ((unsigned)cx >= G) continue;
                    int c = cbase + ((cz * G + cy) * G + cx);
                    int s0 = g_cellstart[c];
                    int e0 = g_cellstart[c + 1];
                    for (int i = s0 + lane; i < e0; i += 32) {
                        float4 t = g_tsorted[i];
                        float ddx = qx - t.x;
                        float ddy = qy - t.y;
                        float ddz = qz - t.z;
                        float d2 = fmaf(ddx, ddx, fmaf(ddy, ddy, ddz * ddz));
                        lbest = fminf(lbest, d2);
                    }
                }
            }
        }
        // Warp-uniform stop test: remaining cells (ring >= r+1) are >= r*h away
        float wm = lbest;
#pragma unroll
        for (int o = 16; o > 0; o >>= 1)
            wm = fminf(wm, __shfl_xor_sync(0xFFFFFFFFu, wm, o));
        wbest = wm;
        float bound = (float)r * GH;
        if (wbest <= bound * bound) break;
    }

    if (lane == 0) g_minbuf[warp] = __float_as_int(wbest);
}

// Stage 1: 64 blocks x 128 threads -> per-block partials (deterministic order)
__global__ void __launch_bounds__(128) reduce1_kernel() {
    __shared__ float sh[4];
    int i = blockIdx.x * 128 + threadIdx.x;   // covers exactly NQ = 8192
    float s = sqrtf(__int_as_float(g_minbuf[i]));
#pragma unroll
    for (int o = 16; o > 0; o >>= 1)
        s += __shfl_down_sync(0xFFFFFFFFu, s, o);
    if ((threadIdx.x & 31) == 0) sh[threadIdx.x >> 5] = s;
    __syncthreads();
    if (threadIdx.x == 0)
        g_partial[blockIdx.x] = sh[0] + sh[1] + sh[2] + sh[3];
}

__global__ void reduce2_kernel(float* __restrict__ out) {
    float s = g_partial[threadIdx.x] + g_partial[threadIdx.x + 32];
#pragma unroll
    for (int o = 16; o > 0; o >>= 1)
        s += __shfl_down_sync(0xFFFFFFFFu, s, o);
    if (threadIdx.x == 0) out[0] = s / (float)NQ;
}

extern "C" void kernel_launch(void* const* d_in, const int* in_sizes, int n_in,
                              void* d_out, int out_size) {
    const float* pred = (const float*)d_in[0];
    const float* target = (const float*)d_in[1];
    const int* idx = (const int*)d_in[2];
    float* out = (float*)d_out;

    zero_kernel<<<NC / 1024, 1024>>>();
    prep_pred_kernel<<<(NQ + 255) / 256, 256>>>(pred, idx);
    count_kernel<<<(NT + 255) / 256, 256>>>(target);
    scan_kernel<<<1, 1024>>>();
    scatter_kernel<<<(NT + 255) / 256, 256>>>();
    query_kernel<<<(NQ * 32 + QTPB - 1) / QTPB, QTPB>>>();
    reduce1_kernel<<<RBLOCKS, 128>>>();
    reduce2_kernel<<<1, 32>>>(out);
}

// round 7
// speedup vs baseline: 2.9467x; 2.9467x over previous
#include <cuda_runtime.h>
#include <cuda_bf16.h>

// Problem constants (fixed by the reference setup_inputs)
#define BB 2
#define NN 8192
#define MM 32768
#define SS 4096
#define NQ (BB * SS)          // 8192 queries
#define NT (BB * MM)          // 65536 targets

// Spatial grid: 64^3 cells per batch over [-6.4, 6.4], h = 0.2
#define G 64
#define GLO (-6.4f)
#define GH 0.2f
#define GINVH 5.0f
#define CELLS_PER_B (G * G * G)       // 262144
#define NC (BB * CELLS_PER_B)         // 524288

// Scan decomposition
#define SCB 512                        // scan blocks
#define SCT 256                        // scan threads per block
#define CPB (NC / SCB)                 // 1024 cells per scan block
#define CPT (CPB / SCT)                // 4 cells per thread

#define RBLOCKS 64

// Device scratch (no allocations allowed)
__device__ float4 g_target4[NT];     // (x, y, z, cell-id-as-int-bits)
__device__ float4 g_tsorted[NT];     // cell-sorted targets
__device__ float4 g_pred4[NQ];       // gathered query points
__device__ int    g_count[NC];
__device__ int    g_fill[NC];
__device__ int    g_cellstart[NC + 1];
__device__ int    g_bsum[SCB];
__device__ int    g_boff[SCB];
__device__ int    g_minbuf[NQ];
__device__ float  g_partial[RBLOCKS];

__global__ void zero_kernel() {
    int i = blockIdx.x * blockDim.x + threadIdx.x;
    if (i < NC) { g_count[i] = 0; g_fill[i] = 0; }
}

__device__ __forceinline__ int cell_coord(float v) {
    int c = (int)((v - GLO) * GINVH);
    return min(max(c, 0), G - 1);
}

__global__ void count_kernel(const float* __restrict__ target) {
    int i = blockIdx.x * blockDim.x + threadIdx.x;
    if (i < NT) {
        float x = target[3 * i + 0];
        float y = target[3 * i + 1];
        float z = target[3 * i + 2];
        int b = i / MM;
        int cell = b * CELLS_PER_B +
                   ((cell_coord(z) * G + cell_coord(y)) * G + cell_coord(x));
        g_target4[i] = make_float4(x, y, z, __int_as_float(cell));
        atomicAdd(&g_count[cell], 1);
    }
}

// ---- 3-stage multi-block exclusive scan over g_count -> g_cellstart ----

// Stage 1: per-block total of 1024 cells
__global__ void __launch_bounds__(SCT) scan1_kernel() {
    __shared__ int wsum[SCT / 32];
    int base = blockIdx.x * CPB + threadIdx.x * CPT;
    int s = 0;
#pragma unroll
    for (int k = 0; k < CPT; k++) s += g_count[base + k];
    int lane = threadIdx.x & 31, wid = threadIdx.x >> 5;
#pragma unroll
    for (int o = 16; o > 0; o >>= 1) s += __shfl_down_sync(0xFFFFFFFFu, s, o);
    if (lane == 0) wsum[wid] = s;
    __syncthreads();
    if (threadIdx.x == 0) {
        int t = 0;
#pragma unroll
        for (int w = 0; w < SCT / 32; w++) t += wsum[w];
        g_bsum[blockIdx.x] = t;
    }
}

// Stage 2: exclusive scan of the 512 block sums (one block).
// NOTE: all 32 lanes of warp 0 must execute the shfl (full-mask contract).
__global__ void __launch_bounds__(SCB) scan2_kernel() {
    __shared__ int wsum[SCB / 32];
    int tid = threadIdx.x;
    int v = g_bsum[tid];
    int lane = tid & 31, wid = tid >> 5;
    int incl = v;
#pragma unroll
    for (int o = 1; o < 32; o <<= 1) {
        int t = __shfl_up_sync(0xFFFFFFFFu, incl, o);
        if (lane >= o) incl += t;
    }
    if (lane == 31) wsum[wid] = incl;
    __syncthreads();
    if (wid == 0) {
        int w = (lane < SCB / 32) ? wsum[lane] : 0;
#pragma unroll
        for (int o = 1; o < 32; o <<= 1) {
            int t = __shfl_up_sync(0xFFFFFFFFu, w, o);
            if (lane >= o) w += t;
        }
        if (lane < SCB / 32) wsum[lane] = w;
    }
    __syncthreads();
    g_boff[tid] = incl - v + (wid > 0 ? wsum[wid - 1] : 0);
}

// Stage 3: per-block local exclusive scan + global offset.
// Same full-warp shfl fix as stage 2.
__global__ void __launch_bounds__(SCT) scan3_kernel() {
    __shared__ int wsum[SCT / 32];
    int base = blockIdx.x * CPB + threadIdx.x * CPT;
    int c[CPT];
    int tsum = 0;
#pragma unroll
    for (int k = 0; k < CPT; k++) { c[k] = g_count[base + k]; tsum += c[k]; }

    int lane = threadIdx.x & 31, wid = threadIdx.x >> 5;
    int incl = tsum;
#pragma unroll
    for (int o = 1; o < 32; o <<= 1) {
        int t = __shfl_up_sync(0xFFFFFFFFu, incl, o);
        if (lane >= o) incl += t;
    }
    if (lane == 31) wsum[wid] = incl;
    __syncthreads();
    if (wid == 0) {
        int w = (lane < SCT / 32) ? wsum[lane] : 0;
#pragma unroll
        for (int o = 1; o < 32; o <<= 1) {
            int t = __shfl_up_sync(0xFFFFFFFFu, w, o);
            if (lane >= o) w += t;
        }
        if (lane < SCT / 32) wsum[lane] = w;
    }
    __syncthreads();
    int run = g_boff[blockIdx.x] + incl - tsum + (wid > 0 ? wsum[wid - 1] : 0);
#pragma unroll
    for (int k = 0; k < CPT; k++) { g_cellstart[base + k] = run; run += c[k]; }
    if (blockIdx.x == 0 && threadIdx.x == 0) g_cellstart[NC] = NT;
}

__global__ void scatter_kernel() {
    int i = blockIdx.x * blockDim.x + threadIdx.x;
    if (i < NT) {
        float4 t = g_target4[i];
        int cell = __float_as_int(t.w);
        int pos = g_cellstart[cell] + atomicAdd(&g_fill[cell], 1);
        g_tsorted[pos] = t;
    }
}

// Gather query points. idx is int32 on device (JAX x64-disabled coerces int64).
__global__ void prep_pred_kernel(const float* __restrict__ pred,
                                 const int* __restrict__ idx) {
    int i = blockIdx.x * blockDim.x + threadIdx.x;
    if (i < NQ) {
        int b = i / SS;
        int s = i % SS;
        int j = min(max(idx[s], 0), NN - 1);
        const float* p = pred + ((long long)b * NN + j) * 3;
        g_pred4[i] = make_float4(p[0], p[1], p[2], 0.0f);
    }
}

// Warp-per-query expanding-box exact NN. Cells are x-contiguous in the sort
// order, so each (cz,cy) row of the box is one contiguous candidate range.
#define QTPB 256
__global__ void __launch_bounds__(QTPB) query_kernel() {
    const int q = blockIdx.x * (QTPB / 32) + (threadIdx.x >> 5);
    const int lane = threadIdx.x & 31;
    if (q >= NQ) return;

    float4 qp = g_pred4[q];
    const float qx = qp.x, qy = qp.y, qz = qp.z;
    const int hx = cell_coord(qx);
    const int hy = cell_coord(qy);
    const int hz = cell_coord(qz);
    const int cbase = (q / SS) * CELLS_PER_B;

    float wbest = __int_as_float(0x7F800000);

    for (int r = 1; r < G; r++) {
        // Scan the full box of Chebyshev radius r (rescans prior box; r>=2 is rare)
        const int x0 = max(hx - r, 0), x1 = min(hx + r, G - 1);
        const int y0 = max(hy - r, 0), y1 = min(hy + r, G - 1);
        const int z0 = max(hz - r, 0), z1 = min(hz + r, G - 1);
        float lbest = __int_as_float(0x7F800000);
        for (int cz = z0; cz <= z1; cz++) {
            for (int cy = y0; cy <= y1; cy++) {
                int rowbase = cbase + (cz * G + cy) * G;
                int s0 = g_cellstart[rowbase + x0];
                int e0 = g_cellstart[rowbase + x1 + 1];
                for (int i = s0 + lane; i < e0; i += 32) {
                    float4 t = g_tsorted[i];
                    float dx = qx - t.x;
                    float dy = qy - t.y;
                    float dz = qz - t.z;
                    float d2 = fmaf(dx, dx, fmaf(dy, dy, dz * dz));
                    lbest = fminf(lbest, d2);
                }
            }
        }
        // All unvisited points are >= r*h away -> exact stop condition
        float wm = lbest;
#pragma unroll
        for (int o = 16; o > 0; o >>= 1)
            wm = fminf(wm, __shfl_xor_sync(0xFFFFFFFFu, wm, o));
        wbest = wm;
        float bound = (float)r * GH;
        if (wbest <= bound * bound) break;
    }

    if (lane == 0) g_minbuf[q] = __float_as_int(wbest);
}

// Deterministic two-stage mean reduction
__global__ void __launch_bounds__(128) reduce1_kernel() {
    __shared__ float sh[4];
    int i = blockIdx.x * 128 + threadIdx.x;
    float s = sqrtf(fmaxf(__int_as_float(g_minbuf[i]), 0.0f));
#pragma unroll
    for (int o = 16; o > 0; o >>= 1)
        s += __shfl_down_sync(0xFFFFFFFFu, s, o);
    if ((threadIdx.x & 31) == 0) sh[threadIdx.x >> 5] = s;
    __syncthreads();
    if (threadIdx.x == 0)
        g_partial[blockIdx.x] = sh[0] + sh[1] + sh[2] + sh[3];
}

__global__ void reduce2_kernel(float* __restrict__ out) {
    float s = g_partial[threadIdx.x] + g_partial[threadIdx.x + 32];
#pragma unroll
    for (int o = 16; o > 0; o >>= 1)
        s += __shfl_down_sync(0xFFFFFFFFu, s, o);
    if (threadIdx.x == 0) out[0] = s / (float)NQ;
}

extern "C" void kernel_launch(void* const* d_in, const int* in_sizes, int n_in,
                              void* d_out, int out_size) {
    const float* pred = (const float*)d_in[0];
    const float* target = (const float*)d_in[1];
    const int* idx = (const int*)d_in[2];
    float* out = (float*)d_out;

    zero_kernel<<<NC / 256, 256>>>();
    prep_pred_kernel<<<(NQ + 255) / 256, 256>>>(pred, idx);
    count_kernel<<<(NT + 255) / 256, 256>>>(target);
    scan1_kernel<<<SCB, SCT>>>();
    scan2_kernel<<<1, SCB>>>();
    scan3_kernel<<<SCB, SCT>>>();
    scatter_kernel<<<(NT + 255) / 256, 256>>>();
    query_kernel<<<NQ / (QTPB / 32), QTPB>>>();
    reduce1_kernel<<<RBLOCKS, 128>>>();
    reduce2_kernel<<<1, 32>>>(out);
}

// round 8
// speedup vs baseline: 3.6636x; 1.2433x over previous
#include <cuda_runtime.h>
#include <cuda_bf16.h>

// Problem constants (fixed by the reference setup_inputs)
#define BB 2
#define NN 8192
#define MM 32768
#define SS 4096
#define NQ (BB * SS)          // 8192 queries
#define NT (BB * MM)          // 65536 targets

// Spatial grid: 32^3 cells per batch over [-4.8, 4.8], h = 0.3
#define G 32
#define GLO (-4.8f)
#define GH 0.3f
#define GINVH 3.33333333f
#define CELLS_PER_B (G * G * G)       // 32768
#define NC (BB * CELLS_PER_B)         // 65536

// Scan decomposition: 64 blocks x 256 threads x 4 cells
#define SCB 64
#define SCT 256
#define CPB (NC / SCB)                 // 1024
#define CPT (CPB / SCT)                // 4

#define RBLOCKS 64

// Device scratch (no allocations allowed). g_count starts zeroed (static init)
// and is returned to exactly zero by scatter_kernel every call -> graph-replay safe.
__device__ float4 g_target4[NT];     // (x, y, z, cell-id-as-int-bits)
__device__ float4 g_tsorted[NT];     // cell-sorted targets
__device__ float4 g_pred4[NQ];       // gathered query points
__device__ int    g_count[NC];
__device__ int    g_cellstart[NC + 1];
__device__ int    g_bsum[SCB];
__device__ int    g_boff[SCB];
__device__ int    g_minbuf[NQ];
__device__ float  g_partial[RBLOCKS];

__device__ __forceinline__ int cell_coord(float v) {
    int c = (int)((v - GLO) * GINVH);
    return min(max(c, 0), G - 1);
}

// Histogram targets + gather queries (fused). idx is int32 on device
// (JAX x64-disabled coerces int64 -> int32).
__global__ void count_prep_kernel(const float* __restrict__ target,
                                  const float* __restrict__ pred,
                                  const int* __restrict__ idx) {
    int i = blockIdx.x * blockDim.x + threadIdx.x;
    if (i < NT) {
        float x = target[3 * i + 0];
        float y = target[3 * i + 1];
        float z = target[3 * i + 2];
        int b = i / MM;
        int cell = b * CELLS_PER_B +
                   ((cell_coord(z) * G + cell_coord(y)) * G + cell_coord(x));
        g_target4[i] = make_float4(x, y, z, __int_as_float(cell));
        atomicAdd(&g_count[cell], 1);
    }
    if (i < NQ) {
        int b = i / SS;
        int s = i % SS;
        int j = min(max(idx[s], 0), NN - 1);
        const float* p = pred + ((long long)b * NN + j) * 3;
        g_pred4[i] = make_float4(p[0], p[1], p[2], 0.0f);
    }
}

// ---- 3-stage multi-block exclusive scan over g_count -> g_cellstart ----

__global__ void __launch_bounds__(SCT) scan1_kernel() {
    __shared__ int wsum[SCT / 32];
    int base = blockIdx.x * CPB + threadIdx.x * CPT;
    int s = 0;
#pragma unroll
    for (int k = 0; k < CPT; k++) s += g_count[base + k];
    int lane = threadIdx.x & 31, wid = threadIdx.x >> 5;
#pragma unroll
    for (int o = 16; o > 0; o >>= 1) s += __shfl_down_sync(0xFFFFFFFFu, s, o);
    if (lane == 0) wsum[wid] = s;
    __syncthreads();
    if (threadIdx.x == 0) {
        int t = 0;
#pragma unroll
        for (int w = 0; w < SCT / 32; w++) t += wsum[w];
        g_bsum[blockIdx.x] = t;
    }
}

// Exclusive scan of the 64 block sums (one block of 64 threads; full-warp shfls).
__global__ void __launch_bounds__(SCB) scan2_kernel() {
    __shared__ int wsum[SCB / 32];
    int tid = threadIdx.x;
    int v = g_bsum[tid];
    int lane = tid & 31, wid = tid >> 5;
    int incl = v;
#pragma unroll
    for (int o = 1; o < 32; o <<= 1) {
        int t = __shfl_up_sync(0xFFFFFFFFu, incl, o);
        if (lane >= o) incl += t;
    }
    if (lane == 31) wsum[wid] = incl;
    __syncthreads();
    int prior = 0;
    for (int w = 0; w < wid; w++) prior += wsum[w];   // SCB/32 = 2: trivial
    g_boff[tid] = prior + incl - v;
}

__global__ void __launch_bounds__(SCT) scan3_kernel() {
    __shared__ int wsum[SCT / 32];
    int base = blockIdx.x * CPB + threadIdx.x * CPT;
    int c[CPT];
    int tsum = 0;
#pragma unroll
    for (int k = 0; k < CPT; k++) { c[k] = g_count[base + k]; tsum += c[k]; }

    int lane = threadIdx.x & 31, wid = threadIdx.x >> 5;
    int incl = tsum;
#pragma unroll
    for (int o = 1; o < 32; o <<= 1) {
        int t = __shfl_up_sync(0xFFFFFFFFu, incl, o);
        if (lane >= o) incl += t;
    }
    if (lane == 31) wsum[wid] = incl;
    __syncthreads();
    if (wid == 0) {
        int w = (lane < SCT / 32) ? wsum[lane] : 0;
#pragma unroll
        for (int o = 1; o < 32; o <<= 1) {
            int t = __shfl_up_sync(0xFFFFFFFFu, w, o);
            if (lane >= o) w += t;
        }
        if (lane < SCT / 32) wsum[lane] = w;
    }
    __syncthreads();
    int run = g_boff[blockIdx.x] + incl - tsum + (wid > 0 ? wsum[wid - 1] : 0);
#pragma unroll
    for (int k = 0; k < CPT; k++) { g_cellstart[base + k] = run; run += c[k]; }
    if (blockIdx.x == 0 && threadIdx.x == 0) g_cellstart[NC] = NT;
}

// Scatter into sorted order. Consumes g_count back to 0 (replay-safe).
__global__ void scatter_kernel() {
    int i = blockIdx.x * blockDim.x + threadIdx.x;
    if (i < NT) {
        float4 t = g_target4[i];
        int cell = __float_as_int(t.w);
        int old = atomicAdd(&g_count[cell], -1);     // old in [1..count]
        g_tsorted[g_cellstart[cell] + old - 1] = t;
    }
}

// Warp-per-query expanding-box exact NN with real-space box-margin bound.
// Cells are x-contiguous in sort order -> each (cz,cy) row is one range.
#define QTPB 256
__global__ void __launch_bounds__(QTPB) query_kernel() {
    const int q = blockIdx.x * (QTPB / 32) + (threadIdx.x >> 5);
    const int lane = threadIdx.x & 31;
    if (q >= NQ) return;

    float4 qp = g_pred4[q];
    const float qx = qp.x, qy = qp.y, qz = qp.z;
    const int hx = cell_coord(qx);
    const int hy = cell_coord(qy);
    const int hz = cell_coord(qz);
    const int cbase = (q / SS) * CELLS_PER_B;
    const float INF = __int_as_float(0x7F800000);

    float wbest = INF;

    for (int r = 1; r < G; r++) {
        const int x0 = max(hx - r, 0), x1 = min(hx + r, G - 1);
        const int y0 = max(hy - r, 0), y1 = min(hy + r, G - 1);
        const int z0 = max(hz - r, 0), z1 = min(hz + r, G - 1);
        float lbest = INF;
        for (int cz = z0; cz <= z1; cz++) {
            for (int cy = y0; cy <= y1; cy++) {
                int rowbase = cbase + (cz * G + cy) * G;
                int s0 = g_cellstart[rowbase + x0];
                int e0 = g_cellstart[rowbase + x1 + 1];
                for (int i = s0 + lane; i < e0; i += 32) {
                    float4 t = g_tsorted[i];
                    float dx = qx - t.x;
                    float dy = qy - t.y;
                    float dz = qz - t.z;
                    float d2 = fmaf(dx, dx, fmaf(dy, dy, dz * dz));
                    lbest = fminf(lbest, d2);
                }
            }
        }
        float wm = lbest;
#pragma unroll
        for (int o = 16; o > 0; o >>= 1)
            wm = fminf(wm, __shfl_xor_sync(0xFFFFFFFFu, wm, o));
        wbest = wm;

        // Exact stop: all unscanned points lie outside the box's real-space
        // extent (edge cells are open: clamped points included -> +inf margin).
        float m = INF;
        if (x0 > 0)     m = fminf(m, qx - (GLO + (float)x0 * GH));
        if (x1 < G - 1) m = fminf(m, (GLO + (float)(x1 + 1) * GH) - qx);
        if (y0 > 0)     m = fminf(m, qy - (GLO + (float)y0 * GH));
        if (y1 < G - 1) m = fminf(m, (GLO + (float)(y1 + 1) * GH) - qy);
        if (z0 > 0)     m = fminf(m, qz - (GLO + (float)z0 * GH));
        if (z1 < G - 1) m = fminf(m, (GLO + (float)(z1 + 1) * GH) - qz);
        m = fmaxf(m, 0.0f);
        if (wbest <= m * m) break;
        if (x0 == 0 && y0 == 0 && z0 == 0 &&
            x1 == G - 1 && y1 == G - 1 && z1 == G - 1) break;  // whole grid scanned
    }

    if (lane == 0) g_minbuf[q] = __float_as_int(wbest);
}

// Deterministic two-stage mean reduction
__global__ void __launch_bounds__(128) reduce1_kernel() {
    __shared__ float sh[4];
    int i = blockIdx.x * 128 + threadIdx.x;
    float s = sqrtf(fmaxf(__int_as_float(g_minbuf[i]), 0.0f));
#pragma unroll
    for (int o = 16; o > 0; o >>= 1)
        s += __shfl_down_sync(0xFFFFFFFFu, s, o);
    if ((threadIdx.x & 31) == 0) sh[threadIdx.x >> 5] = s;
    __syncthreads();
    if (threadIdx.x == 0)
        g_partial[blockIdx.x] = sh[0] + sh[1] + sh[2] + sh[3];
}

__global__ void reduce2_kernel(float* __restrict__ out) {
    float s = g_partial[threadIdx.x] + g_partial[threadIdx.x + 32];
#pragma unroll
    for (int o = 16; o > 0; o >>= 1)
        s += __shfl_down_sync(0xFFFFFFFFu, s, o);
    if (threadIdx.x == 0) out[0] = s / (float)NQ;
}

extern "C" void kernel_launch(void* const* d_in, const int* in_sizes, int n_in,
                              void* d_out, int out_size) {
    const float* pred = (const float*)d_in[0];
    const float* target = (const float*)d_in[1];
    const int* idx = (const int*)d_in[2];
    float* out = (float*)d_out;

    count_prep_kernel<<<NT / 256, 256>>>(target, pred, idx);
    scan1_kernel<<<SCB, SCT>>>();
    scan2_kernel<<<1, SCB>>>();
    scan3_kernel<<<SCB, SCT>>>();
    scatter_kernel<<<NT / 256, 256>>>();
    query_kernel<<<NQ / (QTPB / 32), QTPB>>>();
    reduce1_kernel<<<RBLOCKS, 128>>>();
    reduce2_kernel<<<1, 32>>>(out);
}